// round 2
// baseline (speedup 1.0000x reference)
#include <cuda_runtime.h>

// FocalLoss: loss = sum_b mean_a [ w[a] * (1-p)^2 * BCE(p_clamped, t) ]
// inputs  [B, A] f32, targets [A, B] i32 (0/1), w [A] f32  -> scalar f32
constexpr int BVAL = 1000000;
constexpr int AVAL = 40;
constexpr float EPSF = 1e-12f;
constexpr int TPB = 256;

__device__ double g_acc;

__global__ void zero_acc_kernel() { g_acc = 0.0; }

__global__ void __launch_bounds__(TPB) focal_main_kernel(
    const float* __restrict__ inputs,
    const int*   __restrict__ targets,
    const float* __restrict__ w)
{
    __shared__ float sw[AVAL];
    int tid = threadIdx.x;
    if (tid < AVAL) sw[tid] = w[tid];
    __syncthreads();

    int b = blockIdx.x * TPB + tid;
    float acc = 0.0f;
    if (b < BVAL) {
        const float4* row = reinterpret_cast<const float4*>(inputs + (long)b * AVAL);
        #pragma unroll
        for (int a4 = 0; a4 < AVAL / 4; a4++) {
            float4 p4 = __ldg(row + a4);
            float pv[4] = {p4.x, p4.y, p4.z, p4.w};
            #pragma unroll
            for (int j = 0; j < 4; j++) {
                int a = a4 * 4 + j;
                int t = __ldg(targets + (long)a * BVAL + b);  // coalesced per a
                float p  = pv[j];
                float pc = fminf(fmaxf(p, EPSF), 1.0f - EPSF);
                float arg = t ? pc : (1.0f - pc);   // only one log needed (t is 0/1)
                float bce = -__logf(arg);           // MUFU.LG2 path: keeps us HBM-bound
                float om  = 1.0f - p;               // focal weight uses UNCLAMPED p
                acc = fmaf(sw[a] * om * om, bce, acc);
            }
        }
    }

    // warp reduce
    #pragma unroll
    for (int off = 16; off; off >>= 1)
        acc += __shfl_down_sync(0xffffffffu, acc, off);

    __shared__ float warpsum[TPB / 32];
    if ((tid & 31) == 0) warpsum[tid >> 5] = acc;
    __syncthreads();

    if (tid < TPB / 32) {
        float v = warpsum[tid];
        #pragma unroll
        for (int off = (TPB / 64); off; off >>= 1)
            v += __shfl_down_sync(0xffu, v, off);
        if (tid == 0) atomicAdd(&g_acc, (double)v);
    }
}

__global__ void finalize_kernel(float* __restrict__ out) {
    out[0] = (float)(g_acc * (1.0 / (double)AVAL));
}

extern "C" void kernel_launch(void* const* d_in, const int* in_sizes, int n_in,
                              void* d_out, int out_size)
{
    const float* inputs  = (const float*)d_in[0];   // [B, A]
    const int*   targets = (const int*)  d_in[1];   // [A, B]
    const float* weights = (const float*)d_in[2];   // [A]
    float* out = (float*)d_out;

    zero_acc_kernel<<<1, 1>>>();
    int grid = (BVAL + TPB - 1) / TPB;
    focal_main_kernel<<<grid, TPB>>>(inputs, targets, weights);
    finalize_kernel<<<1, 1>>>(out);
}